// round 1
// baseline (speedup 1.0000x reference)
#include <cuda_runtime.h>

#define BATCH 4
#define SEQ   2048
#define DM    1024
#define MTOT  (BATCH*SEQ)

// Scratch (static device arrays: allocation-free rule)
__device__ float g_Q[(size_t)MTOT * DM];
__device__ float g_K[(size_t)MTOT * DM];
__device__ float g_V[(size_t)MTOT * DM];
__device__ float g_S[(size_t)BATCH * SEQ * SEQ];

constexpr int BM = 128, BN = 128, BK = 16, NTHREADS = 256;

// ---------------------------------------------------------------------------
// 8x8 register micro-tile FMA step on one BK slice already staged in shared.
// ---------------------------------------------------------------------------
__device__ __forceinline__ void mma_steps(const float (*As)[BM],
                                          const float (*Bs)[BN],
                                          float (&acc)[8][8], int tx, int ty)
{
#pragma unroll
    for (int kk = 0; kk < BK; kk++) {
        float4 a0 = *reinterpret_cast<const float4*>(&As[kk][ty * 8]);
        float4 a1 = *reinterpret_cast<const float4*>(&As[kk][ty * 8 + 4]);
        float4 b0 = *reinterpret_cast<const float4*>(&Bs[kk][tx * 8]);
        float4 b1 = *reinterpret_cast<const float4*>(&Bs[kk][tx * 8 + 4]);
        float ra[8] = {a0.x, a0.y, a0.z, a0.w, a1.x, a1.y, a1.z, a1.w};
        float rb[8] = {b0.x, b0.y, b0.z, b0.w, b1.x, b1.y, b1.z, b1.w};
#pragma unroll
        for (int i = 0; i < 8; i++)
#pragma unroll
            for (int j = 0; j < 8; j++)
                acc[i][j] = fmaf(ra[i], rb[j], acc[i][j]);
    }
}

// Stage a BM x BK tile of a K-major (row-major [rows, K]) matrix, transposed
// into As[BK][BM].
__device__ __forceinline__ void load_kmajor(const float* __restrict__ src,
                                            int ld, int rowBase, int k0,
                                            float (*dst)[BM], int tid)
{
    for (int f = tid; f < BM * BK / 4; f += NTHREADS) {
        int row = f >> 2;
        int kc  = (f & 3) << 2;
        float4 v = *reinterpret_cast<const float4*>(
            src + (size_t)(rowBase + row) * ld + k0 + kc);
        dst[kc + 0][row] = v.x;
        dst[kc + 1][row] = v.y;
        dst[kc + 2][row] = v.z;
        dst[kc + 3][row] = v.w;
    }
}

// ---------------------------------------------------------------------------
// Kernel 1: fused QKV projection. C = X * W^T + b  (X:[M,K] row, W:[N,K] row)
// blockIdx.z selects Q / K / V.
// ---------------------------------------------------------------------------
__global__ void __launch_bounds__(NTHREADS)
qkv_kernel(const float* __restrict__ X,
           const float* __restrict__ Wq, const float* __restrict__ bq,
           const float* __restrict__ Wk, const float* __restrict__ bk,
           const float* __restrict__ Wv, const float* __restrict__ bv)
{
    __shared__ float As[BK][BM];
    __shared__ float Bs[BK][BN];

    const float* W;
    const float* bias;
    float* C;
    if (blockIdx.z == 0)      { W = Wq; bias = bq; C = g_Q; }
    else if (blockIdx.z == 1) { W = Wk; bias = bk; C = g_K; }
    else                      { W = Wv; bias = bv; C = g_V; }

    int tid = threadIdx.x;
    int tx = tid & 15, ty = tid >> 4;
    int mBase = blockIdx.x * BM;
    int nBase = blockIdx.y * BN;

    float acc[8][8];
#pragma unroll
    for (int i = 0; i < 8; i++)
#pragma unroll
        for (int j = 0; j < 8; j++) acc[i][j] = 0.0f;

    for (int kt = 0; kt < DM / BK; kt++) {
        int k0 = kt * BK;
        load_kmajor(X, DM, mBase, k0, As, tid);
        // W is [N, K] row-major -> same K-major staging
        load_kmajor(W, DM, nBase, k0, Bs, tid);
        __syncthreads();
        mma_steps(As, Bs, acc, tx, ty);
        __syncthreads();
    }

    int m0 = mBase + ty * 8;
    int n0 = nBase + tx * 8;
#pragma unroll
    for (int i = 0; i < 8; i++) {
        float4 o0, o1;
        o0.x = acc[i][0] + bias[n0 + 0];
        o0.y = acc[i][1] + bias[n0 + 1];
        o0.z = acc[i][2] + bias[n0 + 2];
        o0.w = acc[i][3] + bias[n0 + 3];
        o1.x = acc[i][4] + bias[n0 + 4];
        o1.y = acc[i][5] + bias[n0 + 5];
        o1.z = acc[i][6] + bias[n0 + 6];
        o1.w = acc[i][7] + bias[n0 + 7];
        *reinterpret_cast<float4*>(C + (size_t)(m0 + i) * DM + n0)     = o0;
        *reinterpret_cast<float4*>(C + (size_t)(m0 + i) * DM + n0 + 4) = o1;
    }
}

// ---------------------------------------------------------------------------
// Kernel 2: scores = Q K^T / sqrt(D) per batch, lower-triangle blocks only.
// Masked (upper-triangle) region is never written; softmax writes zeros there.
// ---------------------------------------------------------------------------
__global__ void __launch_bounds__(NTHREADS)
scores_kernel()
{
    int mBase = blockIdx.x * BM;   // query
    int nBase = blockIdx.y * BN;   // key
    if (nBase >= mBase + BM) return;   // fully masked block: skip entirely

    __shared__ float As[BK][BM];
    __shared__ float Bs[BK][BN];

    int b = blockIdx.z;
    const float* Q = g_Q + (size_t)b * SEQ * DM;
    const float* K = g_K + (size_t)b * SEQ * DM;
    float* C = g_S + (size_t)b * SEQ * SEQ;

    int tid = threadIdx.x;
    int tx = tid & 15, ty = tid >> 4;

    float acc[8][8];
#pragma unroll
    for (int i = 0; i < 8; i++)
#pragma unroll
        for (int j = 0; j < 8; j++) acc[i][j] = 0.0f;

    for (int kt = 0; kt < DM / BK; kt++) {
        int k0 = kt * BK;
        load_kmajor(Q, DM, mBase, k0, As, tid);
        load_kmajor(K, DM, nBase, k0, Bs, tid);
        __syncthreads();
        mma_steps(As, Bs, acc, tx, ty);
        __syncthreads();
    }

    const float alpha = 0.03125f;  // 1/sqrt(1024)
    int m0 = mBase + ty * 8;
    int n0 = nBase + tx * 8;
#pragma unroll
    for (int i = 0; i < 8; i++) {
        float4 o0, o1;
        o0.x = acc[i][0] * alpha; o0.y = acc[i][1] * alpha;
        o0.z = acc[i][2] * alpha; o0.w = acc[i][3] * alpha;
        o1.x = acc[i][4] * alpha; o1.y = acc[i][5] * alpha;
        o1.z = acc[i][6] * alpha; o1.w = acc[i][7] * alpha;
        *reinterpret_cast<float4*>(C + (size_t)(m0 + i) * SEQ + n0)     = o0;
        *reinterpret_cast<float4*>(C + (size_t)(m0 + i) * SEQ + n0 + 4) = o1;
    }
}

// ---------------------------------------------------------------------------
// Kernel 3: causal row softmax in place on g_S.
// Row fits in shared (2048 floats). Writes 0 beyond the causal boundary so PV
// can consume full tiles.
// ---------------------------------------------------------------------------
__global__ void __launch_bounds__(256)
softmax_kernel()
{
    __shared__ float buf[SEQ];
    __shared__ float red[256];

    int row = blockIdx.x;          // 0 .. BATCH*SEQ-1
    int b = row / SEQ, q = row % SEQ;
    float* s = g_S + (size_t)b * SEQ * SEQ + (size_t)q * SEQ;
    int len = q + 1;
    int tid = threadIdx.x;

    float mx = -3.4e38f;
    for (int k = tid; k < len; k += 256) {
        float v = s[k];
        buf[k] = v;
        mx = fmaxf(mx, v);
    }
    red[tid] = mx;
    __syncthreads();
#pragma unroll
    for (int off = 128; off > 0; off >>= 1) {
        if (tid < off) red[tid] = fmaxf(red[tid], red[tid + off]);
        __syncthreads();
    }
    mx = red[0];
    __syncthreads();

    float sum = 0.0f;
    for (int k = tid; k < len; k += 256) {
        float e = __expf(buf[k] - mx);
        buf[k] = e;
        sum += e;
    }
    red[tid] = sum;
    __syncthreads();
#pragma unroll
    for (int off = 128; off > 0; off >>= 1) {
        if (tid < off) red[tid] += red[tid + off];
        __syncthreads();
    }
    float inv = 1.0f / red[0];
    __syncthreads();

    for (int k = tid; k < SEQ; k += 256)
        s[k] = (k < len) ? buf[k] * inv : 0.0f;
}

// ---------------------------------------------------------------------------
// Kernel 4: out = P @ V   (NN GEMM; K-loop truncated at causal boundary)
// P: [SEQ, SEQ] row-major, V: [SEQ, DM] row-major.
// ---------------------------------------------------------------------------
__global__ void __launch_bounds__(NTHREADS)
pv_kernel(float* __restrict__ out)
{
    __shared__ float As[BK][BM];
    __shared__ float Bs[BK][BN];

    int b = blockIdx.z;
    const float* P = g_S + (size_t)b * SEQ * SEQ;
    const float* V = g_V + (size_t)b * SEQ * DM;
    float* C = out + (size_t)b * SEQ * DM;

    int tid = threadIdx.x;
    int tx = tid & 15, ty = tid >> 4;
    int mBase = blockIdx.x * BM;   // query rows
    int nBase = blockIdx.y * BN;   // output feature cols

    float acc[8][8];
#pragma unroll
    for (int i = 0; i < 8; i++)
#pragma unroll
        for (int j = 0; j < 8; j++) acc[i][j] = 0.0f;

    // Causal: keys only go up to mBase+BM-1 (P is 0 beyond per-row boundary).
    int kTiles = (mBase + BM) / BK;

    for (int kt = 0; kt < kTiles; kt++) {
        int k0 = kt * BK;
        load_kmajor(P, SEQ, mBase, k0, As, tid);
        // V tile: BK rows x BN cols, direct (no transpose), fully coalesced
        for (int f = tid; f < BK * BN / 4; f += NTHREADS) {
            int row = f >> 5;            // BN/4 = 32 float4 per row
            int nc  = (f & 31) << 2;
            float4 v = *reinterpret_cast<const float4*>(
                V + (size_t)(k0 + row) * DM + nBase + nc);
            *reinterpret_cast<float4*>(&Bs[row][nc]) = v;
        }
        __syncthreads();
        mma_steps(As, Bs, acc, tx, ty);
        __syncthreads();
    }

    int m0 = mBase + ty * 8;
    int n0 = nBase + tx * 8;
#pragma unroll
    for (int i = 0; i < 8; i++) {
        float4 o0 = {acc[i][0], acc[i][1], acc[i][2], acc[i][3]};
        float4 o1 = {acc[i][4], acc[i][5], acc[i][6], acc[i][7]};
        *reinterpret_cast<float4*>(C + (size_t)(m0 + i) * DM + n0)     = o0;
        *reinterpret_cast<float4*>(C + (size_t)(m0 + i) * DM + n0 + 4) = o1;
    }
}

// ---------------------------------------------------------------------------
extern "C" void kernel_launch(void* const* d_in, const int* in_sizes, int n_in,
                              void* d_out, int out_size)
{
    const float* X  = (const float*)d_in[0];
    const float* Wq = (const float*)d_in[1];
    const float* bq = (const float*)d_in[2];
    const float* Wk = (const float*)d_in[3];
    const float* bk = (const float*)d_in[4];
    const float* Wv = (const float*)d_in[5];
    const float* bv = (const float*)d_in[6];
    float* out = (float*)d_out;

    qkv_kernel<<<dim3(MTOT / BM, DM / BN, 3), NTHREADS>>>(X, Wq, bq, Wk, bk, Wv, bv);
    scores_kernel<<<dim3(SEQ / BM, SEQ / BN, BATCH), NTHREADS>>>();
    softmax_kernel<<<BATCH * SEQ, 256>>>();
    pv_kernel<<<dim3(SEQ / BM, DM / BN, BATCH), NTHREADS>>>(out);
}

// round 3
// speedup vs baseline: 3.7023x; 3.7023x over previous
#include <cuda_runtime.h>
#include <cstdint>

#define BATCH 4
#define SEQ   2048
#define DM    1024
#define MTOT  (BATCH*SEQ)

// Scratch (static device arrays: allocation-free rule)
__device__ float g_Q[(size_t)MTOT * DM];
__device__ float g_K[(size_t)MTOT * DM];
__device__ float g_Vt[(size_t)BATCH * DM * SEQ];   // V transposed: [B][DM][SEQ]
__device__ float g_S[(size_t)BATCH * SEQ * SEQ];

// ---------------------------------------------------------------------------
// Tiling: 128x128x32 block, 256 threads, 8 warps as 2(M) x 4(N),
// warp tile 64x32, mma.sync m16n8k8 tf32 (4 m-frags x 4 n-frags).
// ---------------------------------------------------------------------------
constexpr int BM = 128, BN = 128, BK = 32, NTH = 256;
constexpr int BKP = BK + 4;                        // +16B pad: conflict-free LDS
constexpr int STAGE_FLOATS = BM * BKP + BN * BKP;  // 9216
constexpr int DSMEM = 2 * STAGE_FLOATS * 4;        // 73728 B, double buffered

__device__ __forceinline__ uint32_t smem_u32(const void* p) {
    uint32_t a;
    asm("{ .reg .u64 t; cvta.to.shared.u64 t, %1; cvt.u32.u64 %0, t; }"
        : "=r"(a) : "l"(p));
    return a;
}

__device__ __forceinline__ uint32_t f2tf(float f) {
    uint32_t r;
    asm("cvt.rna.tf32.f32 %0, %1;" : "=r"(r) : "f"(f));
    return r;
}

__device__ __forceinline__ void cpasync16(uint32_t s, const float* g) {
    asm volatile("cp.async.cg.shared.global [%0], [%1], 16;" :: "r"(s), "l"(g));
}
#define CP_COMMIT() asm volatile("cp.async.commit_group;" ::: "memory")
#define CP_WAIT(n)  asm volatile("cp.async.wait_group %0;" :: "n"(n) : "memory")

// Issue one k-tile (A and B 128x32 panels) into stage st via cp.async.
__device__ __forceinline__ void issue_tile(
    float* sm, int st,
    const float* __restrict__ A, int lda,
    const float* __restrict__ B, int ldb,
    int mBase, int nBase, int kt, int tid)
{
    float* As = sm + st * STAGE_FLOATS;
    float* Bs = As + BM * BKP;
    const float* Ag = A + (size_t)mBase * lda + kt * BK;
    const float* Bg = B + (size_t)nBase * ldb + kt * BK;
#pragma unroll
    for (int i = 0; i < 4; i++) {
        int f = tid + i * NTH;       // 0..1023
        int r = f >> 3;              // row 0..127
        int c = (f & 7) << 2;        // float col 0,4,..,28
        cpasync16(smem_u32(As + r * BKP + c), Ag + (size_t)r * lda + c);
        cpasync16(smem_u32(Bs + r * BKP + c), Bg + (size_t)r * ldb + c);
    }
    CP_COMMIT();
}

// One BK=32 slice of MMAs from staged SMEM.
__device__ __forceinline__ void compute_tile(
    const float* __restrict__ As, const float* __restrict__ Bs,
    float (&acc)[16][4], int warpM, int warpN, int lane)
{
    const int gr = lane >> 2;   // 0..7
    const int tc = lane & 3;    // 0..3
#pragma unroll
    for (int ks = 0; ks < 4; ks++) {
        const int k0 = ks * 8 + tc;
        uint32_t a[4][4];
#pragma unroll
        for (int mi = 0; mi < 4; mi++) {
            const float* base = As + (size_t)(warpM * 64 + mi * 16 + gr) * BKP + k0;
            a[mi][0] = f2tf(base[0]);
            a[mi][1] = f2tf(base[8 * BKP]);
            a[mi][2] = f2tf(base[4]);
            a[mi][3] = f2tf(base[8 * BKP + 4]);
        }
        uint32_t b[4][2];
#pragma unroll
        for (int ni = 0; ni < 4; ni++) {
            const float* base = Bs + (size_t)(warpN * 32 + ni * 8 + gr) * BKP + k0;
            b[ni][0] = f2tf(base[0]);
            b[ni][1] = f2tf(base[4]);
        }
#pragma unroll
        for (int mi = 0; mi < 4; mi++)
#pragma unroll
            for (int ni = 0; ni < 4; ni++) {
                float* c = acc[mi * 4 + ni];
                asm volatile(
                    "mma.sync.aligned.m16n8k8.row.col.f32.tf32.tf32.f32 "
                    "{%0,%1,%2,%3}, {%4,%5,%6,%7}, {%8,%9}, {%0,%1,%2,%3};"
                    : "+f"(c[0]), "+f"(c[1]), "+f"(c[2]), "+f"(c[3])
                    : "r"(a[mi][0]), "r"(a[mi][1]), "r"(a[mi][2]), "r"(a[mi][3]),
                      "r"(b[ni][0]), "r"(b[ni][1]));
            }
    }
}

// Full TN mainloop: acc = A[mBase:+128, :] * B[nBase:+128, :]^T over kTiles*32 K.
__device__ __forceinline__ void gemm_main(
    const float* __restrict__ A, int lda,
    const float* __restrict__ B, int ldb,
    int mBase, int nBase, int kTiles, float (&acc)[16][4])
{
    extern __shared__ float sm[];
    const int tid = threadIdx.x;
    const int wid = tid >> 5, lane = tid & 31;
    const int warpM = wid & 1, warpN = wid >> 1;

#pragma unroll
    for (int i = 0; i < 16; i++)
#pragma unroll
        for (int j = 0; j < 4; j++) acc[i][j] = 0.0f;

    issue_tile(sm, 0, A, lda, B, ldb, mBase, nBase, 0, tid);

    for (int kt = 0; kt < kTiles; kt++) {
        if (kt + 1 < kTiles) {
            issue_tile(sm, (kt + 1) & 1, A, lda, B, ldb, mBase, nBase, kt + 1, tid);
            CP_WAIT(1);
        } else {
            CP_WAIT(0);
        }
        __syncthreads();
        const float* As = sm + (kt & 1) * STAGE_FLOATS;
        compute_tile(As, As + BM * BKP, acc, warpM, warpN, lane);
        __syncthreads();
    }
}

// ---------------------------------------------------------------------------
// Kernel 1: QKV projection. z=0 -> Q, z=1 -> K (row-major), z=2 -> Vt.
// ---------------------------------------------------------------------------
__global__ void __launch_bounds__(NTH)
qkv_mma(const float* __restrict__ X,
        const float* __restrict__ Wq, const float* __restrict__ bq,
        const float* __restrict__ Wk, const float* __restrict__ bk,
        const float* __restrict__ Wv, const float* __restrict__ bv)
{
    const int z = blockIdx.z;
    const float* W;
    const float* bias;
    if (z == 0)      { W = Wq; bias = bq; }
    else if (z == 1) { W = Wk; bias = bk; }
    else             { W = Wv; bias = bv; }

    const int mBase = blockIdx.x * BM;
    const int nBase = blockIdx.y * BN;

    float acc[16][4];
    gemm_main(X, DM, W, DM, mBase, nBase, DM / BK, acc);

    const int wid = threadIdx.x >> 5, lane = threadIdx.x & 31;
    const int warpM = wid & 1, warpN = wid >> 1;
    const int gr = lane >> 2, tc = lane & 3;

    if (z < 2) {
        float* C = (z == 0 ? g_Q : g_K);
#pragma unroll
        for (int mi = 0; mi < 4; mi++) {
            int r0 = mBase + warpM * 64 + mi * 16 + gr;
#pragma unroll
            for (int ni = 0; ni < 4; ni++) {
                int n = nBase + warpN * 32 + ni * 8 + 2 * tc;
                const float* c = acc[mi * 4 + ni];
                float2 lo = {c[0] + bias[n], c[1] + bias[n + 1]};
                float2 hi = {c[2] + bias[n], c[3] + bias[n + 1]};
                *reinterpret_cast<float2*>(C + (size_t)r0 * DM + n) = lo;
                *reinterpret_cast<float2*>(C + (size_t)(r0 + 8) * DM + n) = hi;
            }
        }
    } else {
        // transposed store: Vt[b][n][tok]
#pragma unroll
        for (int mi = 0; mi < 4; mi++) {
            int r0 = mBase + warpM * 64 + mi * 16 + gr;   // global token
            int bat = r0 / SEQ;
            int t0  = r0 % SEQ;
            float* C = g_Vt + (size_t)bat * DM * SEQ;
#pragma unroll
            for (int ni = 0; ni < 4; ni++) {
                int n = nBase + warpN * 32 + ni * 8 + 2 * tc;
                const float* c = acc[mi * 4 + ni];
                C[(size_t)n * SEQ + t0]           = c[0] + bias[n];
                C[(size_t)(n + 1) * SEQ + t0]     = c[1] + bias[n + 1];
                C[(size_t)n * SEQ + t0 + 8]       = c[2] + bias[n];
                C[(size_t)(n + 1) * SEQ + t0 + 8] = c[3] + bias[n + 1];
            }
        }
    }
}

// ---------------------------------------------------------------------------
// Kernel 2: scores = Q K^T / 32, lower-triangle blocks only.
// ---------------------------------------------------------------------------
__global__ void __launch_bounds__(NTH)
scores_mma()
{
    const int mBase = blockIdx.x * BM;
    const int nBase = blockIdx.y * BN;
    if (nBase >= mBase + BM) return;   // fully masked block

    const int bat = blockIdx.z;
    const float* Q = g_Q + (size_t)bat * SEQ * DM;
    const float* K = g_K + (size_t)bat * SEQ * DM;
    float* C = g_S + (size_t)bat * SEQ * SEQ;

    float acc[16][4];
    gemm_main(Q, DM, K, DM, mBase, nBase, DM / BK, acc);

    const int wid = threadIdx.x >> 5, lane = threadIdx.x & 31;
    const int warpM = wid & 1, warpN = wid >> 1;
    const int gr = lane >> 2, tc = lane & 3;
    const float alpha = 0.03125f;   // 1/sqrt(1024)

#pragma unroll
    for (int mi = 0; mi < 4; mi++) {
        int r0 = mBase + warpM * 64 + mi * 16 + gr;
#pragma unroll
        for (int ni = 0; ni < 4; ni++) {
            int n = nBase + warpN * 32 + ni * 8 + 2 * tc;
            const float* c = acc[mi * 4 + ni];
            float2 lo = {c[0] * alpha, c[1] * alpha};
            float2 hi = {c[2] * alpha, c[3] * alpha};
            *reinterpret_cast<float2*>(C + (size_t)r0 * SEQ + n) = lo;
            *reinterpret_cast<float2*>(C + (size_t)(r0 + 8) * SEQ + n) = hi;
        }
    }
}

// ---------------------------------------------------------------------------
// Kernel 3: causal row softmax in place on g_S (zero-fills masked tail).
// ---------------------------------------------------------------------------
__global__ void __launch_bounds__(256)
softmax_kernel()
{
    __shared__ float buf[SEQ];
    __shared__ float red[256];

    int rowid = blockIdx.x;
    int b = rowid / SEQ, q = rowid % SEQ;
    float* s = g_S + (size_t)b * SEQ * SEQ + (size_t)q * SEQ;
    int len = q + 1;
    int tid = threadIdx.x;

    float mx = -3.4e38f;
    for (int k = tid; k < len; k += 256) {
        float v = s[k];
        buf[k] = v;
        mx = fmaxf(mx, v);
    }
    red[tid] = mx;
    __syncthreads();
#pragma unroll
    for (int off = 128; off > 0; off >>= 1) {
        if (tid < off) red[tid] = fmaxf(red[tid], red[tid + off]);
        __syncthreads();
    }
    mx = red[0];
    __syncthreads();

    float sum = 0.0f;
    for (int k = tid; k < len; k += 256) {
        float e = __expf(buf[k] - mx);
        buf[k] = e;
        sum += e;
    }
    red[tid] = sum;
    __syncthreads();
#pragma unroll
    for (int off = 128; off > 0; off >>= 1) {
        if (tid < off) red[tid] += red[tid + off];
        __syncthreads();
    }
    float inv = 1.0f / red[0];
    __syncthreads();

    for (int k = tid; k < SEQ; k += 256)
        s[k] = (k < len) ? buf[k] * inv : 0.0f;
}

// ---------------------------------------------------------------------------
// Kernel 4: out = P @ V via Vt (K-major). K loop truncated at causal boundary.
// ---------------------------------------------------------------------------
__global__ void __launch_bounds__(NTH)
pv_mma(float* __restrict__ out)
{
    const int mBase = blockIdx.x * BM;
    const int nBase = blockIdx.y * BN;
    const int bat = blockIdx.z;

    const float* P  = g_S  + (size_t)bat * SEQ * SEQ;
    const float* Vt = g_Vt + (size_t)bat * DM * SEQ;
    float* C = out + (size_t)bat * SEQ * DM;

    float acc[16][4];
    gemm_main(P, SEQ, Vt, SEQ, mBase, nBase, (mBase + BM) / BK, acc);

    const int wid = threadIdx.x >> 5, lane = threadIdx.x & 31;
    const int warpM = wid & 1, warpN = wid >> 1;
    const int gr = lane >> 2, tc = lane & 3;

#pragma unroll
    for (int mi = 0; mi < 4; mi++) {
        int r0 = mBase + warpM * 64 + mi * 16 + gr;
#pragma unroll
        for (int ni = 0; ni < 4; ni++) {
            int n = nBase + warpN * 32 + ni * 8 + 2 * tc;
            const float* c = acc[mi * 4 + ni];
            float2 lo = {c[0], c[1]};
            float2 hi = {c[2], c[3]};
            *reinterpret_cast<float2*>(C + (size_t)r0 * DM + n) = lo;
            *reinterpret_cast<float2*>(C + (size_t)(r0 + 8) * DM + n) = hi;
        }
    }
}

// ---------------------------------------------------------------------------
extern "C" void kernel_launch(void* const* d_in, const int* in_sizes, int n_in,
                              void* d_out, int out_size)
{
    const float* X  = (const float*)d_in[0];
    const float* Wq = (const float*)d_in[1];
    const float* bq = (const float*)d_in[2];
    const float* Wk = (const float*)d_in[3];
    const float* bk = (const float*)d_in[4];
    const float* Wv = (const float*)d_in[5];
    const float* bv = (const float*)d_in[6];
    float* out = (float*)d_out;

    cudaFuncSetAttribute(qkv_mma,    cudaFuncAttributeMaxDynamicSharedMemorySize, DSMEM);
    cudaFuncSetAttribute(scores_mma, cudaFuncAttributeMaxDynamicSharedMemorySize, DSMEM);
    cudaFuncSetAttribute(pv_mma,     cudaFuncAttributeMaxDynamicSharedMemorySize, DSMEM);

    qkv_mma<<<dim3(MTOT / BM, DM / BN, 3), NTH, DSMEM>>>(X, Wq, bq, Wk, bk, Wv, bv);
    scores_mma<<<dim3(SEQ / BM, SEQ / BN, BATCH), NTH, DSMEM>>>();
    softmax_kernel<<<BATCH * SEQ, 256>>>();
    pv_mma<<<dim3(SEQ / BM, DM / BN, BATCH), NTH, DSMEM>>>(out);
}

// round 4
// speedup vs baseline: 4.3817x; 1.1835x over previous
#include <cuda_runtime.h>
#include <cstdint>

#define BATCH 4
#define SEQ   2048
#define DM    1024
#define MTOT  (BATCH*SEQ)

// Scratch (static device arrays: allocation-free rule)
__device__ float g_Q [(size_t)MTOT * DM];            // tf32-rounded
__device__ float g_K [(size_t)MTOT * DM];            // tf32-rounded
__device__ float g_Vt[(size_t)BATCH * DM * SEQ];     // V^T, tf32-rounded
__device__ float g_S [(size_t)BATCH * SEQ * SEQ];    // scores -> P (P tf32-rounded)
__device__ float g_Xr[(size_t)MTOT * DM];            // tf32-rounded input
__device__ float g_Wr[3][(size_t)DM * DM];           // tf32-rounded weights

// ---------------------------------------------------------------------------
// Tiling: 128x128x32 block, 128 threads, 4 warps as 2(M) x 2(N),
// warp tile 64x64, mma.sync m16n8k8 tf32 (4 m-frags x 8 n-frags).
// Operands are pre-rounded to tf32 -> no cvt in the mainloop.
// ---------------------------------------------------------------------------
constexpr int BM = 128, BN = 128, BK = 32, NTH = 128;
constexpr int BKP = BK + 4;                        // pad: conflict-free LDS
constexpr int STAGE_FLOATS = (BM + BN) * BKP;      // 9216
constexpr int DSMEM = 2 * STAGE_FLOATS * 4;        // 73728 B double buffered

__device__ __forceinline__ uint32_t smem_u32(const void* p) {
    uint32_t a;
    asm("{ .reg .u64 t; cvta.to.shared.u64 t, %1; cvt.u32.u64 %0, t; }"
        : "=r"(a) : "l"(p));
    return a;
}

__device__ __forceinline__ uint32_t f2tf(float f) {
    uint32_t r;
    asm("cvt.rna.tf32.f32 %0, %1;" : "=r"(r) : "f"(f));
    return r;
}
__device__ __forceinline__ float rnd(float f) { return __uint_as_float(f2tf(f)); }

__device__ __forceinline__ void cpasync16(uint32_t s, const float* g) {
    asm volatile("cp.async.cg.shared.global [%0], [%1], 16;" :: "r"(s), "l"(g));
}
#define CP_COMMIT() asm volatile("cp.async.commit_group;" ::: "memory")
#define CP_WAIT(n)  asm volatile("cp.async.wait_group %0;" :: "n"(n) : "memory")

// ---------------------------------------------------------------------------
// Pre-pass: round a tensor to tf32 (which: 0 -> g_Xr, 1..3 -> g_Wr[which-1]).
// ---------------------------------------------------------------------------
__global__ void __launch_bounds__(256)
round_tf32_kernel(const float* __restrict__ src, int which, int n4)
{
    float* dst = (which == 0) ? g_Xr : g_Wr[which - 1];
    int i = blockIdx.x * 256 + threadIdx.x;
    if (i < n4) {
        float4 v = reinterpret_cast<const float4*>(src)[i];
        v.x = rnd(v.x); v.y = rnd(v.y); v.z = rnd(v.z); v.w = rnd(v.w);
        reinterpret_cast<float4*>(dst)[i] = v;
    }
}

// Issue one k-tile (A and B 128x32 panels) into stage st via cp.async.
__device__ __forceinline__ void issue_tile(
    float* sm, int st,
    const float* __restrict__ A, int lda,
    const float* __restrict__ B, int ldb,
    int mBase, int nBase, int kt, int tid)
{
    float* As = sm + st * STAGE_FLOATS;
    float* Bs = As + BM * BKP;
    const float* Ag = A + (size_t)mBase * lda + kt * BK;
    const float* Bg = B + (size_t)nBase * ldb + kt * BK;
#pragma unroll
    for (int i = 0; i < 8; i++) {
        int f = tid + i * NTH;       // 0..1023
        int r = f >> 3;              // row 0..127
        int c = (f & 7) << 2;        // float col 0,4,..,28
        cpasync16(smem_u32(As + r * BKP + c), Ag + (size_t)r * lda + c);
        cpasync16(smem_u32(Bs + r * BKP + c), Bg + (size_t)r * ldb + c);
    }
    CP_COMMIT();
}

// One BK=32 slice of MMAs from staged SMEM (raw tf32 bits, no cvt).
__device__ __forceinline__ void compute_tile(
    const uint32_t* __restrict__ As, const uint32_t* __restrict__ Bs,
    float (&acc)[32][4], int warpM, int warpN, int lane)
{
    const int gr = lane >> 2;   // 0..7
    const int tc = lane & 3;    // 0..3
#pragma unroll
    for (int ks = 0; ks < 4; ks++) {
        const int k0 = ks * 8 + tc;
        uint32_t a[4][4];
#pragma unroll
        for (int mi = 0; mi < 4; mi++) {
            const uint32_t* base = As + (size_t)(warpM * 64 + mi * 16 + gr) * BKP + k0;
            a[mi][0] = base[0];
            a[mi][1] = base[8 * BKP];
            a[mi][2] = base[4];
            a[mi][3] = base[8 * BKP + 4];
        }
        uint32_t b[8][2];
#pragma unroll
        for (int ni = 0; ni < 8; ni++) {
            const uint32_t* base = Bs + (size_t)(warpN * 64 + ni * 8 + gr) * BKP + k0;
            b[ni][0] = base[0];
            b[ni][1] = base[4];
        }
#pragma unroll
        for (int mi = 0; mi < 4; mi++)
#pragma unroll
            for (int ni = 0; ni < 8; ni++) {
                float* c = acc[mi * 8 + ni];
                asm volatile(
                    "mma.sync.aligned.m16n8k8.row.col.f32.tf32.tf32.f32 "
                    "{%0,%1,%2,%3}, {%4,%5,%6,%7}, {%8,%9}, {%0,%1,%2,%3};"
                    : "+f"(c[0]), "+f"(c[1]), "+f"(c[2]), "+f"(c[3])
                    : "r"(a[mi][0]), "r"(a[mi][1]), "r"(a[mi][2]), "r"(a[mi][3]),
                      "r"(b[ni][0]), "r"(b[ni][1]));
            }
    }
}

// Full TN mainloop: acc = A[mBase:+128, :] * B[nBase:+128, :]^T over kTiles*32 K.
__device__ __forceinline__ void gemm_main(
    const float* __restrict__ A, int lda,
    const float* __restrict__ B, int ldb,
    int mBase, int nBase, int kTiles, float (&acc)[32][4])
{
    extern __shared__ float sm[];
    const int tid = threadIdx.x;
    const int wid = tid >> 5, lane = tid & 31;
    const int warpM = wid & 1, warpN = wid >> 1;

#pragma unroll
    for (int i = 0; i < 32; i++)
#pragma unroll
        for (int j = 0; j < 4; j++) acc[i][j] = 0.0f;

    issue_tile(sm, 0, A, lda, B, ldb, mBase, nBase, 0, tid);

    for (int kt = 0; kt < kTiles; kt++) {
        if (kt + 1 < kTiles) {
            issue_tile(sm, (kt + 1) & 1, A, lda, B, ldb, mBase, nBase, kt + 1, tid);
            CP_WAIT(1);
        } else {
            CP_WAIT(0);
        }
        __syncthreads();
        const uint32_t* As = reinterpret_cast<const uint32_t*>(sm + (kt & 1) * STAGE_FLOATS);
        compute_tile(As, As + BM * BKP, acc, warpM, warpN, lane);
        __syncthreads();
    }
}

// ---------------------------------------------------------------------------
// Kernel 1: QKV projection from pre-rounded g_Xr / g_Wr.
// z=0 -> Q, z=1 -> K (row-major, tf32-rounded), z=2 -> Vt (transposed, rounded).
// ---------------------------------------------------------------------------
__global__ void __launch_bounds__(NTH)
qkv_mma(const float* __restrict__ bq,
        const float* __restrict__ bk,
        const float* __restrict__ bv)
{
    const int z = blockIdx.z;
    const float* bias = (z == 0) ? bq : (z == 1) ? bk : bv;
    const float* W = g_Wr[z];

    const int mBase = blockIdx.x * BM;
    const int nBase = blockIdx.y * BN;

    float acc[32][4];
    gemm_main(g_Xr, DM, W, DM, mBase, nBase, DM / BK, acc);

    const int wid = threadIdx.x >> 5, lane = threadIdx.x & 31;
    const int warpM = wid & 1, warpN = wid >> 1;
    const int gr = lane >> 2, tc = lane & 3;

    if (z < 2) {
        float* C = (z == 0 ? g_Q : g_K);
#pragma unroll
        for (int mi = 0; mi < 4; mi++) {
            int r0 = mBase + warpM * 64 + mi * 16 + gr;
#pragma unroll
            for (int ni = 0; ni < 8; ni++) {
                int n = nBase + warpN * 64 + ni * 8 + 2 * tc;
                const float* c = acc[mi * 8 + ni];
                float2 lo = {rnd(c[0] + bias[n]), rnd(c[1] + bias[n + 1])};
                float2 hi = {rnd(c[2] + bias[n]), rnd(c[3] + bias[n + 1])};
                *reinterpret_cast<float2*>(C + (size_t)r0 * DM + n) = lo;
                *reinterpret_cast<float2*>(C + (size_t)(r0 + 8) * DM + n) = hi;
            }
        }
    } else {
        // transposed store: Vt[b][n][tok]
#pragma unroll
        for (int mi = 0; mi < 4; mi++) {
            int r0 = mBase + warpM * 64 + mi * 16 + gr;   // global token
            int bat = r0 / SEQ;
            int t0  = r0 % SEQ;
            float* C = g_Vt + (size_t)bat * DM * SEQ;
#pragma unroll
            for (int ni = 0; ni < 8; ni++) {
                int n = nBase + warpN * 64 + ni * 8 + 2 * tc;
                const float* c = acc[mi * 8 + ni];
                C[(size_t)n * SEQ + t0]           = rnd(c[0] + bias[n]);
                C[(size_t)(n + 1) * SEQ + t0]     = rnd(c[1] + bias[n + 1]);
                C[(size_t)n * SEQ + t0 + 8]       = rnd(c[2] + bias[n]);
                C[(size_t)(n + 1) * SEQ + t0 + 8] = rnd(c[3] + bias[n + 1]);
            }
        }
    }
}

// ---------------------------------------------------------------------------
// Kernel 2: scores = Q K^T / 32, lower-triangle blocks only (fp32 out).
// ---------------------------------------------------------------------------
__global__ void __launch_bounds__(NTH)
scores_mma()
{
    const int mBase = blockIdx.x * BM;
    const int nBase = blockIdx.y * BN;
    if (nBase >= mBase + BM) return;   // fully masked block

    const int bat = blockIdx.z;
    const float* Q = g_Q + (size_t)bat * SEQ * DM;
    const float* K = g_K + (size_t)bat * SEQ * DM;
    float* C = g_S + (size_t)bat * SEQ * SEQ;

    float acc[32][4];
    gemm_main(Q, DM, K, DM, mBase, nBase, DM / BK, acc);

    const int wid = threadIdx.x >> 5, lane = threadIdx.x & 31;
    const int warpM = wid & 1, warpN = wid >> 1;
    const int gr = lane >> 2, tc = lane & 3;
    const float alpha = 0.03125f;   // 1/sqrt(1024)

#pragma unroll
    for (int mi = 0; mi < 4; mi++) {
        int r0 = mBase + warpM * 64 + mi * 16 + gr;
#pragma unroll
        for (int ni = 0; ni < 8; ni++) {
            int n = nBase + warpN * 64 + ni * 8 + 2 * tc;
            const float* c = acc[mi * 8 + ni];
            float2 lo = {c[0] * alpha, c[1] * alpha};
            float2 hi = {c[2] * alpha, c[3] * alpha};
            *reinterpret_cast<float2*>(C + (size_t)r0 * SEQ + n) = lo;
            *reinterpret_cast<float2*>(C + (size_t)(r0 + 8) * SEQ + n) = hi;
        }
    }
}

// ---------------------------------------------------------------------------
// Kernel 3: causal row softmax in place on g_S.
// Output P is tf32-rounded (PV MMA consumes it); masked tail zero-filled.
// ---------------------------------------------------------------------------
__global__ void __launch_bounds__(256)
softmax_kernel()
{
    __shared__ float buf[SEQ];
    __shared__ float red[256];

    int rowid = blockIdx.x;
    int b = rowid / SEQ, q = rowid % SEQ;
    float* s = g_S + (size_t)b * SEQ * SEQ + (size_t)q * SEQ;
    int len = q + 1;
    int tid = threadIdx.x;

    float mx = -3.4e38f;
    for (int k = tid; k < len; k += 256) {
        float v = s[k];
        buf[k] = v;
        mx = fmaxf(mx, v);
    }
    red[tid] = mx;
    __syncthreads();
#pragma unroll
    for (int off = 128; off > 0; off >>= 1) {
        if (tid < off) red[tid] = fmaxf(red[tid], red[tid + off]);
        __syncthreads();
    }
    mx = red[0];
    __syncthreads();

    float sum = 0.0f;
    for (int k = tid; k < len; k += 256) {
        float e = __expf(buf[k] - mx);
        buf[k] = e;
        sum += e;
    }
    red[tid] = sum;
    __syncthreads();
#pragma unroll
    for (int off = 128; off > 0; off >>= 1) {
        if (tid < off) red[tid] += red[tid + off];
        __syncthreads();
    }
    float inv = 1.0f / red[0];
    __syncthreads();

    for (int k = tid; k < SEQ; k += 256)
        s[k] = (k < len) ? rnd(buf[k] * inv) : 0.0f;
}

// ---------------------------------------------------------------------------
// Kernel 4: out = P @ V via Vt (K-major). K loop truncated at causal boundary.
// ---------------------------------------------------------------------------
__global__ void __launch_bounds__(NTH)
pv_mma(float* __restrict__ out)
{
    const int mBase = blockIdx.x * BM;
    const int nBase = blockIdx.y * BN;
    const int bat = blockIdx.z;

    const float* P  = g_S  + (size_t)bat * SEQ * SEQ;
    const float* Vt = g_Vt + (size_t)bat * DM * SEQ;
    float* C = out + (size_t)bat * SEQ * DM;

    float acc[32][4];
    gemm_main(P, SEQ, Vt, SEQ, mBase, nBase, (mBase + BM) / BK, acc);

    const int wid = threadIdx.x >> 5, lane = threadIdx.x & 31;
    const int warpM = wid & 1, warpN = wid >> 1;
    const int gr = lane >> 2, tc = lane & 3;

#pragma unroll
    for (int mi = 0; mi < 4; mi++) {
        int r0 = mBase + warpM * 64 + mi * 16 + gr;
#pragma unroll
        for (int ni = 0; ni < 8; ni++) {
            int n = nBase + warpN * 64 + ni * 8 + 2 * tc;
            const float* c = acc[mi * 8 + ni];
            float2 lo = {c[0], c[1]};
            float2 hi = {c[2], c[3]};
            *reinterpret_cast<float2*>(C + (size_t)r0 * DM + n) = lo;
            *reinterpret_cast<float2*>(C + (size_t)(r0 + 8) * DM + n) = hi;
        }
    }
}

// ---------------------------------------------------------------------------
extern "C" void kernel_launch(void* const* d_in, const int* in_sizes, int n_in,
                              void* d_out, int out_size)
{
    const float* X  = (const float*)d_in[0];
    const float* Wq = (const float*)d_in[1];
    const float* bq = (const float*)d_in[2];
    const float* Wk = (const float*)d_in[3];
    const float* bk = (const float*)d_in[4];
    const float* Wv = (const float*)d_in[5];
    const float* bv = (const float*)d_in[6];
    float* out = (float*)d_out;

    cudaFuncSetAttribute(qkv_mma,    cudaFuncAttributeMaxDynamicSharedMemorySize, DSMEM);
    cudaFuncSetAttribute(scores_mma, cudaFuncAttributeMaxDynamicSharedMemorySize, DSMEM);
    cudaFuncSetAttribute(pv_mma,     cudaFuncAttributeMaxDynamicSharedMemorySize, DSMEM);

    const int nX4 = MTOT * DM / 4, nW4 = DM * DM / 4;
    round_tf32_kernel<<<(nX4 + 255) / 256, 256>>>(X,  0, nX4);
    round_tf32_kernel<<<(nW4 + 255) / 256, 256>>>(Wq, 1, nW4);
    round_tf32_kernel<<<(nW4 + 255) / 256, 256>>>(Wk, 2, nW4);
    round_tf32_kernel<<<(nW4 + 255) / 256, 256>>>(Wv, 3, nW4);

    qkv_mma<<<dim3(MTOT / BM, DM / BN, 3), NTH, DSMEM>>>(bq, bk, bv);
    scores_mma<<<dim3(SEQ / BM, SEQ / BN, BATCH), NTH, DSMEM>>>();
    softmax_kernel<<<BATCH * SEQ, 256>>>();
    pv_mma<<<dim3(SEQ / BM, DM / BN, BATCH), NTH, DSMEM>>>(out);
}